// round 14
// baseline (speedup 1.0000x reference)
#include <cuda_runtime.h>
#include <cuda_bf16.h>

// GatedMemoryModule via bf16x3 split m16n8k16 mma.sync, ldmatrix fragments,
// register-resident attention (no smem round-trip between the two GEMMs).
//   sim  = x @ M^T   : xh*Mh + xl*Mh + xh*Ml
//   attn = softmax(sim)        (stays in accumulator registers; D-layout ==
//                               A-layout for bf16x2 pairs -> direct repack)
//   read = attn @ M  : ah*Mh + al*Mh + ah*Ml
//   gate folded into GEMM1 as memory slot 64 (M padded to 80 rows)
//   out  = x + g*(read - x)
//
// 152 persistent CTAs x 256 threads (8 warps). Tile = 256 rows, 32 rows/warp
// (two m16 blocks) -> B fragments amortized over 2x rows. Warps fully
// self-contained; no __syncthreads in the main loop.

#define NROWS   1000000
#define TILE_M  256
#define NTILES  3907            // ceil(1e6/256); last tile has 64 valid rows
#define GRID    152
#define THREADS 256

// smem u32-index offsets
#define OFF_XH   0              // x hi [256][64] bf16x2 pairs (64KB)
#define OFF_XL   16384          // x lo (64KB)
#define OFF_MH   32768          // M hi [80][64]; row64=gate_w, 65..79=0 (20KB)
#define OFF_ML   37888          // M lo (20KB)
#define SMEM_U32 43008
#define SMEM_BYTES (SMEM_U32 * 4)      // 172,032 B

static __device__ __forceinline__ void bsplit(float v, float& h, float& l) {
    h = __bfloat162float(__float2bfloat16_rn(v));
    l = v - h;
}
static __device__ __forceinline__ unsigned pk(float a, float b) {
    __nv_bfloat162 t = __floats2bfloat162_rn(a, b);   // a -> low half
    return *reinterpret_cast<unsigned*>(&t);
}
static __device__ __forceinline__ float2 up(unsigned u) {
    __nv_bfloat162 b = *reinterpret_cast<__nv_bfloat162*>(&u);
    return __bfloat1622float2(b);
}
static __device__ __forceinline__ void bmma(float* d, const unsigned* a,
                                            const unsigned* b) {
    asm volatile(
        "mma.sync.aligned.m16n8k16.row.col.f32.bf16.bf16.f32 "
        "{%0,%1,%2,%3}, {%4,%5,%6,%7}, {%8,%9}, {%0,%1,%2,%3};"
        : "+f"(d[0]), "+f"(d[1]), "+f"(d[2]), "+f"(d[3])
        : "r"(a[0]), "r"(a[1]), "r"(a[2]), "r"(a[3]), "r"(b[0]), "r"(b[1]));
}
static __device__ __forceinline__ void ldsm4(unsigned* r, unsigned a) {
    asm volatile("ldmatrix.sync.aligned.m8n8.x4.shared.b16 {%0,%1,%2,%3}, [%4];"
        : "=r"(r[0]), "=r"(r[1]), "=r"(r[2]), "=r"(r[3]) : "r"(a));
}
static __device__ __forceinline__ void ldsm4t(unsigned* r, unsigned a) {
    asm volatile("ldmatrix.sync.aligned.m8n8.x4.trans.shared.b16 {%0,%1,%2,%3}, [%4];"
        : "=r"(r[0]), "=r"(r[1]), "=r"(r[2]), "=r"(r[3]) : "r"(a));
}

__global__ void __launch_bounds__(THREADS, 1)
gm_preg(const float* __restrict__ x, const float* __restrict__ memory,
        const float* __restrict__ gate_w, const float* __restrict__ gate_b,
        float* __restrict__ out)
{
    extern __shared__ unsigned shu[];
    const int tid  = threadIdx.x;
    const int w    = tid >> 5, lane = tid & 31;
    const int g    = lane >> 2, cp = lane & 3;
    const int q    = lane & 7, mi = lane >> 3;
    const int g4   = 4 * g;

    // ---- one-time staging: M hi/lo [80][64]; row 64 = gate_w, 65..79 = 0 ----
    for (int i = tid; i < 80 * 64; i += THREADS) {
        const int s = i >> 6, j = i & 63;
        float v0 = 0.f, v1 = 0.f;
        if (s < 64)       { v0 = memory[s * 128 + 2 * j];
                            v1 = memory[s * 128 + 2 * j + 1]; }
        else if (s == 64) { v0 = gate_w[2 * j]; v1 = gate_w[2 * j + 1]; }
        float h0, l0, h1, l1;
        bsplit(v0, h0, l0); bsplit(v1, h1, l1);
        const int c = j ^ (4 * (s & 7));
        shu[OFF_MH + s * 64 + c] = pk(h0, h1);
        shu[OFF_ML + s * 64 + c] = pk(l0, l1);
    }
    const float gbv = gate_b[0];
    __syncthreads();

    // ---- per-lane ldmatrix base addresses (byte, shared space) ----
    const unsigned shb = (unsigned)__cvta_generic_to_shared(shu);
    const int rowbase = w * 32;
    const int rowA    = rowbase + ((mi & 1) << 3) + q;   // mt=0; mt=1 adds 16
    const unsigned q4  = 4u * q;
    const unsigned cA  = 4u * (mi >> 1);
    const unsigned cB  = 4u * (mi & 1);
    const unsigned cB2 = 4u * (mi >> 1);
    const unsigned aXH  = shb + OFF_XH * 4 + 256u * rowA;
    const unsigned aXL  = shb + OFF_XL * 4 + 256u * rowA;
    const unsigned aMH1 = shb + OFF_MH * 4 + 256u * (8 * (mi >> 1) + q);
    const unsigned aML1 = shb + OFF_ML * 4 + 256u * (8 * (mi >> 1) + q);
    const unsigned aMH2 = shb + OFF_MH * 4 + 256u * (8 * (mi & 1) + q);
    const unsigned aML2 = shb + OFF_ML * 4 + 256u * (8 * (mi & 1) + q);

    unsigned* XH = shu + OFF_XH;  unsigned* XL = shu + OFF_XL;

    for (int t = blockIdx.x; t < NTILES; t += GRID) {
        const long r0 = (long)t * TILE_M;

        // ---- load x tile (32 rows): bf16 hi/lo split into swizzled smem ----
#pragma unroll 4
        for (int i = 0; i < 32; i++) {
            const int row = rowbase + i;
            const long gr = r0 + row;
            float4 xv = make_float4(0.f, 0.f, 0.f, 0.f);
            if (gr < NROWS) xv = ((const float4*)x)[gr * 32 + lane];
            float h0, l0, h1, l1, h2, l2, h3, l3;
            bsplit(xv.x, h0, l0); bsplit(xv.y, h1, l1);
            bsplit(xv.z, h2, l2); bsplit(xv.w, h3, l3);
            const int c = (2 * lane) ^ (4 * (row & 7));
            *(uint2*)(XH + row * 64 + c) = make_uint2(pk(h0, h1), pk(h2, h3));
            *(uint2*)(XL + row * 64 + c) = make_uint2(pk(l0, l1), pk(l2, l3));
        }
        __syncwarp();

        // ---- phase 1: sim[32][64] (+gate) = x @ M^T, 3-term bf16 ----
        float acc1[2][8][4];
        float accg[2][4];
#pragma unroll
        for (int mt = 0; mt < 2; mt++) {
#pragma unroll
            for (int nt = 0; nt < 8; nt++)
#pragma unroll
                for (int j = 0; j < 4; j++) acc1[mt][nt][j] = 0.f;
#pragma unroll
            for (int j = 0; j < 4; j++) accg[mt][j] = 0.f;
        }

        unsigned bA[2][16], bB[2][32], bG[8];
        {   // preload kt=0
            const unsigned ka = 4u * (cA ^ q4);
            ldsm4(bA[0] + 0,  aXH + ka);
            ldsm4(bA[0] + 4,  aXL + ka);
            ldsm4(bA[0] + 8,  aXH + 4096u + ka);
            ldsm4(bA[0] + 12, aXL + 4096u + ka);
            const unsigned kb = 4u * (cB ^ q4);
#pragma unroll
            for (int p = 0; p < 4; p++) {
                ldsm4(bB[0] + 8 * p,     aMH1 + 4096u * p + kb);
                ldsm4(bB[0] + 8 * p + 4, aML1 + 4096u * p + kb);
            }
        }
#pragma unroll
        for (int kt = 0; kt < 8; kt++) {
            const int cur = kt & 1, nxt = cur ^ 1;
            {   // gate tile (M rows 64..79), current kt
                const unsigned kbg = 4u * ((8u * kt + cB) ^ q4);
                ldsm4(bG + 0, aMH1 + 16384u + kbg);
                ldsm4(bG + 4, aML1 + 16384u + kbg);
            }
            if (kt < 7) {                      // prefetch next kt
                const unsigned ka = 4u * ((8u * (kt + 1) + cA) ^ q4);
                ldsm4(bA[nxt] + 0,  aXH + ka);
                ldsm4(bA[nxt] + 4,  aXL + ka);
                ldsm4(bA[nxt] + 8,  aXH + 4096u + ka);
                ldsm4(bA[nxt] + 12, aXL + 4096u + ka);
                const unsigned kb = 4u * ((8u * (kt + 1) + cB) ^ q4);
#pragma unroll
                for (int p = 0; p < 4; p++) {
                    ldsm4(bB[nxt] + 8 * p,     aMH1 + 4096u * p + kb);
                    ldsm4(bB[nxt] + 8 * p + 4, aML1 + 4096u * p + kb);
                }
            }
#pragma unroll
            for (int p = 0; p < 4; p++) {
                unsigned* B = bB[cur] + 8 * p;
#pragma unroll
                for (int mt = 0; mt < 2; mt++) {
                    unsigned* A = bA[cur] + 8 * mt;
                    bmma(acc1[mt][2 * p],     A,     B);       // Ah*Bh
                    bmma(acc1[mt][2 * p + 1], A,     B + 2);
                    bmma(acc1[mt][2 * p],     A + 4, B);       // Al*Bh
                    bmma(acc1[mt][2 * p + 1], A + 4, B + 2);
                    bmma(acc1[mt][2 * p],     A,     B + 4);   // Ah*Bl
                    bmma(acc1[mt][2 * p + 1], A,     B + 6);
                }
            }
#pragma unroll
            for (int mt = 0; mt < 2; mt++) {
                unsigned* A = bA[cur] + 8 * mt;
                bmma(accg[mt], A,     bG);
                bmma(accg[mt], A + 4, bG);
                bmma(accg[mt], A,     bG + 4);
            }
        }

        // ---- gate: col 64 lives at cp==0 regs [0]/[2]; quad-broadcast ----
        float gv[2][2];
#pragma unroll
        for (int mt = 0; mt < 2; mt++) {
            const float s0 = 1.f / (1.f + __expf(-(accg[mt][0] + gbv)));
            const float s1 = 1.f / (1.f + __expf(-(accg[mt][2] + gbv)));
            gv[mt][0] = __shfl_sync(0xffffffffu, s0, lane & ~3);
            gv[mt][1] = __shfl_sync(0xffffffffu, s1, lane & ~3);
        }

        // ---- softmax in-register (quad owns a row) ----
#pragma unroll
        for (int mt = 0; mt < 2; mt++)
#pragma unroll
            for (int h = 0; h < 2; h++) {
                float mx = -3.0e38f;
#pragma unroll
                for (int nt = 0; nt < 8; nt++)
                    mx = fmaxf(mx, fmaxf(acc1[mt][nt][2 * h],
                                         acc1[mt][nt][2 * h + 1]));
                mx = fmaxf(mx, __shfl_xor_sync(0xffffffffu, mx, 1));
                mx = fmaxf(mx, __shfl_xor_sync(0xffffffffu, mx, 2));
                float sum = 0.f;
#pragma unroll
                for (int nt = 0; nt < 8; nt++) {
                    const float e0 = __expf(acc1[mt][nt][2 * h] - mx);
                    const float e1 = __expf(acc1[mt][nt][2 * h + 1] - mx);
                    acc1[mt][nt][2 * h] = e0; acc1[mt][nt][2 * h + 1] = e1;
                    sum += e0 + e1;
                }
                sum += __shfl_xor_sync(0xffffffffu, sum, 1);
                sum += __shfl_xor_sync(0xffffffffu, sum, 2);
                const float inv = 1.0f / sum;
#pragma unroll
                for (int nt = 0; nt < 8; nt++) {
                    acc1[mt][nt][2 * h]     *= inv;
                    acc1[mt][nt][2 * h + 1] *= inv;
                }
            }

        // ---- pack attn into phase-2 A fragments (D-layout == A-layout) ----
        unsigned PH[2][4][4], PL[2][4][4];
#pragma unroll
        for (int mt = 0; mt < 2; mt++)
#pragma unroll
            for (int kt = 0; kt < 4; kt++) {
                const float* d0 = acc1[mt][2 * kt];
                const float* d1 = acc1[mt][2 * kt + 1];
                const unsigned h0 = pk(d0[0], d0[1]);
                const unsigned h1 = pk(d0[2], d0[3]);
                const unsigned h2 = pk(d1[0], d1[1]);
                const unsigned h3 = pk(d1[2], d1[3]);
                PH[mt][kt][0] = h0; PH[mt][kt][1] = h1;
                PH[mt][kt][2] = h2; PH[mt][kt][3] = h3;
                const float2 f0 = up(h0), f1 = up(h1), f2 = up(h2), f3 = up(h3);
                PL[mt][kt][0] = pk(d0[0] - f0.x, d0[1] - f0.y);
                PL[mt][kt][1] = pk(d0[2] - f1.x, d0[3] - f1.y);
                PL[mt][kt][2] = pk(d1[0] - f2.x, d1[1] - f2.y);
                PL[mt][kt][3] = pk(d1[2] - f3.x, d1[3] - f3.y);
            }

        // ---- phase 2 (two n-halves): read = attn @ M, 3-term bf16 ----
#pragma unroll 1
        for (int hf = 0; hf < 2; hf++) {
            float acc2[2][8][4];
#pragma unroll
            for (int mt = 0; mt < 2; mt++)
#pragma unroll
                for (int nt = 0; nt < 8; nt++)
#pragma unroll
                    for (int j = 0; j < 4; j++) acc2[mt][nt][j] = 0.f;

            unsigned bB2[2][8];
            {   // preload step 0 (kt=0, np=0)
                const unsigned cb = 4u * (((unsigned)(4 * hf) * 8 + cB2) ^ q4);
                ldsm4t(bB2[0] + 0, aMH2 + cb);
                ldsm4t(bB2[0] + 4, aML2 + cb);
            }
#pragma unroll
            for (int kt = 0; kt < 4; kt++) {
#pragma unroll
                for (int np = 0; np < 4; np++) {
                    const int s = 4 * kt + np;
                    if (s < 15) {               // prefetch next step's B
                        const int ns = s + 1, nkt = ns >> 2, nnp = ns & 3;
                        const unsigned cb =
                            4u * (((unsigned)(nnp + 4 * hf) * 8 + cB2) ^ q4);
                        ldsm4t(bB2[ns & 1] + 0, aMH2 + 4096u * nkt + cb);
                        ldsm4t(bB2[ns & 1] + 4, aML2 + 4096u * nkt + cb);
                    }
                    unsigned* B = bB2[s & 1];
#pragma unroll
                    for (int mt = 0; mt < 2; mt++) {
                        unsigned* A  = PH[mt][kt];
                        unsigned* Al = PL[mt][kt];
                        bmma(acc2[mt][2 * np],     A,  B);       // Ah*Bh
                        bmma(acc2[mt][2 * np + 1], A,  B + 2);
                        bmma(acc2[mt][2 * np],     Al, B);       // Al*Bh
                        bmma(acc2[mt][2 * np + 1], Al, B + 2);
                        bmma(acc2[mt][2 * np],     A,  B + 4);   // Ah*Bl
                        bmma(acc2[mt][2 * np + 1], A,  B + 6);
                    }
                }
            }

            // ---- epilogue for this n-half: out = x + g*(read - x) ----
#pragma unroll
            for (int mt = 0; mt < 2; mt++)
#pragma unroll
                for (int h = 0; h < 2; h++) {
                    const int row = rowbase + 16 * mt + 8 * h + g;
                    const long gr = r0 + row;
                    if (gr >= NROWS) continue;
                    const float gvv = gv[mt][h];
                    float* orow = out + gr * 128;
#pragma unroll
                    for (int nt = 0; nt < 8; nt++) {
                        const int c = (32 * hf + 4 * nt + cp) ^ g4;
                        const float2 xh = up(XH[row * 64 + c]);
                        const float2 xl = up(XL[row * 64 + c]);
                        const float xx0 = xh.x + xl.x, xx1 = xh.y + xl.y;
                        float2 o;
                        o.x = fmaf(gvv, acc2[mt][nt][2 * h] - xx0, xx0);
                        o.y = fmaf(gvv, acc2[mt][nt][2 * h + 1] - xx1, xx1);
                        *(float2*)(orow + 64 * hf + 8 * nt + 2 * cp) = o;
                    }
                }
        }
        __syncwarp();   // XH/XL reused next iteration
    }
}

extern "C" void kernel_launch(void* const* d_in, const int* in_sizes, int n_in,
                              void* d_out, int out_size) {
    const float* x      = (const float*)d_in[0];
    const float* memory = (const float*)d_in[1];
    const float* gate_w = (const float*)d_in[2];
    const float* gate_b = (const float*)d_in[3];
    float* out = (float*)d_out;
    (void)in_sizes; (void)n_in; (void)out_size;

    cudaFuncSetAttribute(gm_preg,
                         cudaFuncAttributeMaxDynamicSharedMemorySize, SMEM_BYTES);
    gm_preg<<<GRID, THREADS, SMEM_BYTES>>>(x, memory, gate_w, gate_b, out);
}

// round 15
// speedup vs baseline: 1.2135x; 1.2135x over previous
#include <cuda_runtime.h>
#include <cuda_bf16.h>

// GatedMemoryModule via bf16x3 split m16n8k16 mma.sync + ldmatrix fragments +
// register-resident attention.
//   sim  = x @ M^T   : xh*Mh + xl*Mh + xh*Ml
//   attn = softmax(sim)     (kept in accumulator registers; D-layout ==
//                            A-layout for bf16x2 pairs -> direct repack)
//   read = attn @ M  : ah*Mh + al*Mh + ah*Ml   (two n-halves, acc2 32 regs)
//   gate folded into GEMM1 as memory slot 64 (M padded to 80 rows)
//   out  = x + g*(read - x)
//
// 152 persistent CTAs x 384 threads (12 warps = 3/SMSP, the R13-proven
// occupancy). Tile = 192 rows, 16 rows/warp, warps fully self-contained.
// R14 lesson: never trade warps/SMSP for crossbar relief.

#define NROWS   1000000
#define TILE_M  192
#define NTILES  5209            // ceil(1e6/192)
#define GRID    152
#define THREADS 384

// smem u32-index offsets
#define OFF_XH   0              // x hi [192][64] bf16x2 pairs (48KB)
#define OFF_XL   12288          // x lo (48KB)
#define OFF_MH   24576          // M hi [80][64]; row64=gate_w, 65..79=0 (20KB)
#define OFF_ML   29696          // M lo (20KB)
#define SMEM_U32 34816
#define SMEM_BYTES (SMEM_U32 * 4)      // 139,264 B

static __device__ __forceinline__ void bsplit(float v, float& h, float& l) {
    h = __bfloat162float(__float2bfloat16_rn(v));
    l = v - h;
}
static __device__ __forceinline__ unsigned pk(float a, float b) {
    __nv_bfloat162 t = __floats2bfloat162_rn(a, b);   // a -> low half
    return *reinterpret_cast<unsigned*>(&t);
}
static __device__ __forceinline__ float2 up(unsigned u) {
    __nv_bfloat162 b = *reinterpret_cast<__nv_bfloat162*>(&u);
    return __bfloat1622float2(b);
}
static __device__ __forceinline__ void bmma(float* d, const unsigned* a,
                                            const unsigned* b) {
    asm volatile(
        "mma.sync.aligned.m16n8k16.row.col.f32.bf16.bf16.f32 "
        "{%0,%1,%2,%3}, {%4,%5,%6,%7}, {%8,%9}, {%0,%1,%2,%3};"
        : "+f"(d[0]), "+f"(d[1]), "+f"(d[2]), "+f"(d[3])
        : "r"(a[0]), "r"(a[1]), "r"(a[2]), "r"(a[3]), "r"(b[0]), "r"(b[1]));
}
static __device__ __forceinline__ void ldsm4(unsigned* r, unsigned a) {
    asm volatile("ldmatrix.sync.aligned.m8n8.x4.shared.b16 {%0,%1,%2,%3}, [%4];"
        : "=r"(r[0]), "=r"(r[1]), "=r"(r[2]), "=r"(r[3]) : "r"(a));
}
static __device__ __forceinline__ void ldsm4t(unsigned* r, unsigned a) {
    asm volatile("ldmatrix.sync.aligned.m8n8.x4.trans.shared.b16 {%0,%1,%2,%3}, [%4];"
        : "=r"(r[0]), "=r"(r[1]), "=r"(r[2]), "=r"(r[3]) : "r"(a));
}

__global__ void __launch_bounds__(THREADS, 1)
gm_fuse(const float* __restrict__ x, const float* __restrict__ memory,
        const float* __restrict__ gate_w, const float* __restrict__ gate_b,
        float* __restrict__ out)
{
    extern __shared__ unsigned shu[];
    const int tid  = threadIdx.x;
    const int w    = tid >> 5, lane = tid & 31;
    const int g    = lane >> 2, cp = lane & 3;
    const int q    = lane & 7, mi = lane >> 3;
    const int g4   = 4 * g;

    // ---- one-time staging: M hi/lo [80][64]; row 64 = gate_w, 65..79 = 0 ----
    for (int i = tid; i < 80 * 64; i += THREADS) {
        const int s = i >> 6, j = i & 63;
        float v0 = 0.f, v1 = 0.f;
        if (s < 64)       { v0 = memory[s * 128 + 2 * j];
                            v1 = memory[s * 128 + 2 * j + 1]; }
        else if (s == 64) { v0 = gate_w[2 * j]; v1 = gate_w[2 * j + 1]; }
        float h0, l0, h1, l1;
        bsplit(v0, h0, l0); bsplit(v1, h1, l1);
        const int c = j ^ (4 * (s & 7));
        shu[OFF_MH + s * 64 + c] = pk(h0, h1);
        shu[OFF_ML + s * 64 + c] = pk(l0, l1);
    }
    const float gbv = gate_b[0];
    __syncthreads();

    // ---- per-lane ldmatrix base addresses (byte, shared space) ----
    const unsigned shb = (unsigned)__cvta_generic_to_shared(shu);
    const int rowbase = w * 16;
    const int rowA    = rowbase + ((mi & 1) << 3) + q;
    const unsigned q4  = 4u * q;
    const unsigned cA  = 4u * (mi >> 1);
    const unsigned cB  = 4u * (mi & 1);
    const unsigned cB2 = 4u * (mi >> 1);
    const unsigned aXH  = shb + OFF_XH * 4 + 256u * rowA;
    const unsigned aXL  = shb + OFF_XL * 4 + 256u * rowA;
    const unsigned aMH1 = shb + OFF_MH * 4 + 256u * (8 * (mi >> 1) + q);
    const unsigned aML1 = shb + OFF_ML * 4 + 256u * (8 * (mi >> 1) + q);
    const unsigned aMH2 = shb + OFF_MH * 4 + 256u * (8 * (mi & 1) + q);
    const unsigned aML2 = shb + OFF_ML * 4 + 256u * (8 * (mi & 1) + q);

    unsigned* XH = shu + OFF_XH;  unsigned* XL = shu + OFF_XL;

    for (int t = blockIdx.x; t < NTILES; t += GRID) {
        const long r0 = (long)t * TILE_M;

        // ---- load x tile: bf16 hi/lo split into packed swizzled smem ----
#pragma unroll 4
        for (int i = 0; i < 16; i++) {
            const int row = rowbase + i;
            const long gr = r0 + row;
            float4 xv = make_float4(0.f, 0.f, 0.f, 0.f);
            if (gr < NROWS) xv = ((const float4*)x)[gr * 32 + lane];
            float h0, l0, h1, l1, h2, l2, h3, l3;
            bsplit(xv.x, h0, l0); bsplit(xv.y, h1, l1);
            bsplit(xv.z, h2, l2); bsplit(xv.w, h3, l3);
            const int c = (2 * lane) ^ (4 * (row & 7));
            *(uint2*)(XH + row * 64 + c) = make_uint2(pk(h0, h1), pk(h2, h3));
            *(uint2*)(XL + row * 64 + c) = make_uint2(pk(l0, l1), pk(l2, l3));
        }
        __syncwarp();

        // ---- phase 1: sim[16][64] (+gate col 64) = x @ M^T, 3-term bf16 ----
        float acc1[8][4], accg[4];
#pragma unroll
        for (int nt = 0; nt < 8; nt++)
#pragma unroll
            for (int j = 0; j < 4; j++) acc1[nt][j] = 0.f;
#pragma unroll
        for (int j = 0; j < 4; j++) accg[j] = 0.f;

        unsigned bA[2][8], bB[2][32], bG[8];
        {   // preload kt=0
            const unsigned ka = 4u * (cA ^ q4);
            ldsm4(bA[0] + 0, aXH + ka);
            ldsm4(bA[0] + 4, aXL + ka);
            const unsigned kb = 4u * (cB ^ q4);
#pragma unroll
            for (int p = 0; p < 4; p++) {
                ldsm4(bB[0] + 8 * p,     aMH1 + 4096u * p + kb);
                ldsm4(bB[0] + 8 * p + 4, aML1 + 4096u * p + kb);
            }
        }
#pragma unroll
        for (int kt = 0; kt < 8; kt++) {
            const int cur = kt & 1, nxt = cur ^ 1;
            {   // gate tile (M rows 64..79), current kt
                const unsigned kbg = 4u * ((8u * kt + cB) ^ q4);
                ldsm4(bG + 0, aMH1 + 16384u + kbg);
                ldsm4(bG + 4, aML1 + 16384u + kbg);
            }
            if (kt < 7) {                      // prefetch next kt
                const unsigned ka = 4u * ((8u * (kt + 1) + cA) ^ q4);
                ldsm4(bA[nxt] + 0, aXH + ka);
                ldsm4(bA[nxt] + 4, aXL + ka);
                const unsigned kb = 4u * ((8u * (kt + 1) + cB) ^ q4);
#pragma unroll
                for (int p = 0; p < 4; p++) {
                    ldsm4(bB[nxt] + 8 * p,     aMH1 + 4096u * p + kb);
                    ldsm4(bB[nxt] + 8 * p + 4, aML1 + 4096u * p + kb);
                }
            }
            unsigned* A = bA[cur];
#pragma unroll
            for (int p = 0; p < 4; p++) {
                unsigned* B = bB[cur] + 8 * p;
                bmma(acc1[2 * p],     A,     B);       // Ah*Bh
                bmma(acc1[2 * p + 1], A,     B + 2);
                bmma(acc1[2 * p],     A + 4, B);       // Al*Bh
                bmma(acc1[2 * p + 1], A + 4, B + 2);
                bmma(acc1[2 * p],     A,     B + 4);   // Ah*Bl
                bmma(acc1[2 * p + 1], A,     B + 6);
            }
            bmma(accg, A,     bG);                     // gate column
            bmma(accg, A + 4, bG);
            bmma(accg, A,     bG + 4);
        }

        // ---- gate: col 64 lives in cp==0 lanes' regs [0]/[2]; broadcast ----
        float gv[2];
        {
            const float s0 = 1.f / (1.f + __expf(-(accg[0] + gbv)));
            const float s1 = 1.f / (1.f + __expf(-(accg[2] + gbv)));
            gv[0] = __shfl_sync(0xffffffffu, s0, lane & ~3);
            gv[1] = __shfl_sync(0xffffffffu, s1, lane & ~3);
        }

        // ---- softmax in-register (quad owns a row) ----
#pragma unroll
        for (int h = 0; h < 2; h++) {
            float mx = -3.0e38f;
#pragma unroll
            for (int nt = 0; nt < 8; nt++)
                mx = fmaxf(mx, fmaxf(acc1[nt][2 * h], acc1[nt][2 * h + 1]));
            mx = fmaxf(mx, __shfl_xor_sync(0xffffffffu, mx, 1));
            mx = fmaxf(mx, __shfl_xor_sync(0xffffffffu, mx, 2));
            float sum = 0.f;
#pragma unroll
            for (int nt = 0; nt < 8; nt++) {
                const float e0 = __expf(acc1[nt][2 * h] - mx);
                const float e1 = __expf(acc1[nt][2 * h + 1] - mx);
                acc1[nt][2 * h] = e0; acc1[nt][2 * h + 1] = e1;
                sum += e0 + e1;
            }
            sum += __shfl_xor_sync(0xffffffffu, sum, 1);
            sum += __shfl_xor_sync(0xffffffffu, sum, 2);
            const float inv = 1.0f / sum;
#pragma unroll
            for (int nt = 0; nt < 8; nt++) {
                acc1[nt][2 * h]     *= inv;
                acc1[nt][2 * h + 1] *= inv;
            }
        }

        // ---- pack attn into phase-2 A fragments (D-layout == A-layout) ----
        unsigned PH[4][4], PL[4][4];
#pragma unroll
        for (int kt = 0; kt < 4; kt++) {
            const float* d0 = acc1[2 * kt];
            const float* d1 = acc1[2 * kt + 1];
            const unsigned h0 = pk(d0[0], d0[1]);
            const unsigned h1 = pk(d0[2], d0[3]);
            const unsigned h2 = pk(d1[0], d1[1]);
            const unsigned h3 = pk(d1[2], d1[3]);
            PH[kt][0] = h0; PH[kt][1] = h1; PH[kt][2] = h2; PH[kt][3] = h3;
            const float2 f0 = up(h0), f1 = up(h1), f2 = up(h2), f3 = up(h3);
            PL[kt][0] = pk(d0[0] - f0.x, d0[1] - f0.y);
            PL[kt][1] = pk(d0[2] - f1.x, d0[3] - f1.y);
            PL[kt][2] = pk(d1[0] - f2.x, d1[1] - f2.y);
            PL[kt][3] = pk(d1[2] - f3.x, d1[3] - f3.y);
        }

        // ---- phase 2 (two n-halves): read = attn @ M, 3-term bf16 ----
#pragma unroll 1
        for (int hf = 0; hf < 2; hf++) {
            float acc2[8][4];
#pragma unroll
            for (int nt = 0; nt < 8; nt++)
#pragma unroll
                for (int j = 0; j < 4; j++) acc2[nt][j] = 0.f;

            unsigned bB2[2][8];
            {   // preload step 0 (kt=0, np=0)
                const unsigned cb = 4u * (((unsigned)(4 * hf) * 8 + cB2) ^ q4);
                ldsm4t(bB2[0] + 0, aMH2 + cb);
                ldsm4t(bB2[0] + 4, aML2 + cb);
            }
#pragma unroll
            for (int kt = 0; kt < 4; kt++) {
#pragma unroll
                for (int np = 0; np < 4; np++) {
                    const int s = 4 * kt + np;
                    if (s < 15) {               // prefetch next step's B
                        const int ns = s + 1, nkt = ns >> 2, nnp = ns & 3;
                        const unsigned cb =
                            4u * (((unsigned)(nnp + 4 * hf) * 8 + cB2) ^ q4);
                        ldsm4t(bB2[ns & 1] + 0, aMH2 + 4096u * nkt + cb);
                        ldsm4t(bB2[ns & 1] + 4, aML2 + 4096u * nkt + cb);
                    }
                    unsigned* B  = bB2[s & 1];
                    unsigned* A  = PH[kt];
                    unsigned* Al = PL[kt];
                    bmma(acc2[2 * np],     A,  B);       // Ah*Bh
                    bmma(acc2[2 * np + 1], A,  B + 2);
                    bmma(acc2[2 * np],     Al, B);       // Al*Bh
                    bmma(acc2[2 * np + 1], Al, B + 2);
                    bmma(acc2[2 * np],     A,  B + 4);   // Ah*Bl
                    bmma(acc2[2 * np + 1], A,  B + 6);
                }
            }

            // ---- epilogue for this n-half: out = x + g*(read - x) ----
#pragma unroll
            for (int h = 0; h < 2; h++) {
                const int row = rowbase + 8 * h + g;
                const long gr = r0 + row;
                if (gr >= NROWS) continue;
                const float gvv = gv[h];
                float* orow = out + gr * 128;
#pragma unroll
                for (int nt = 0; nt < 8; nt++) {
                    const int c = (32 * hf + 4 * nt + cp) ^ g4;
                    const float2 xh = up(XH[row * 64 + c]);
                    const float2 xl = up(XL[row * 64 + c]);
                    const float xx0 = xh.x + xl.x, xx1 = xh.y + xl.y;
                    float2 o;
                    o.x = fmaf(gvv, acc2[nt][2 * h] - xx0, xx0);
                    o.y = fmaf(gvv, acc2[nt][2 * h + 1] - xx1, xx1);
                    *(float2*)(orow + 64 * hf + 8 * nt + 2 * cp) = o;
                }
            }
        }
        __syncwarp();   // XH/XL reused next iteration
    }
}

extern "C" void kernel_launch(void* const* d_in, const int* in_sizes, int n_in,
                              void* d_out, int out_size) {
    const float* x      = (const float*)d_in[0];
    const float* memory = (const float*)d_in[1];
    const float* gate_w = (const float*)d_in[2];
    const float* gate_b = (const float*)d_in[3];
    float* out = (float*)d_out;
    (void)in_sizes; (void)n_in; (void)out_size;

    cudaFuncSetAttribute(gm_fuse,
                         cudaFuncAttributeMaxDynamicSharedMemorySize, SMEM_BYTES);
    gm_fuse<<<GRID, THREADS, SMEM_BYTES>>>(x, memory, gate_w, gate_b, out);
}